// round 17
// baseline (speedup 1.0000x reference)
#include <cuda_runtime.h>
#include <cuda_fp16.h>
#include <math.h>
#include <stdint.h>

// Problem constants
#define B  2
#define S  2048
#define D  1024
#define H  16
#define DK 64
#define M_ROWS (B * S)   // 4096
#define GK 1024
#define GN 1024
#define SZA (M_ROWS * D)

// ---------------- scratch (device globals: allocation-free) ----------------
__device__ __half g_Ah[7][SZA];
__device__ __half g_Wh[4][D * D];   // weights fp16, layout [k][n]
__device__ int g_gidx[B * S];
__device__ int g_cnt[B];

struct FPtr5 { const float* p[5]; };

__device__ __forceinline__ uint32_t smem_u32(const void* p) {
    uint32_t a;
    asm("{ .reg .u64 t; cvta.to.shared.u64 t, %1; cvt.u32.u64 %0, t; }"
        : "=r"(a) : "l"(p));
    return a;
}
__device__ __forceinline__ void ldsm_x4(uint32_t (&r)[4], uint32_t addr) {
    asm volatile("ldmatrix.sync.aligned.m8n8.x4.shared.b16 {%0,%1,%2,%3}, [%4];"
                 : "=r"(r[0]), "=r"(r[1]), "=r"(r[2]), "=r"(r[3]) : "r"(addr));
}
__device__ __forceinline__ void ldsm_x4_t(uint32_t (&r)[4], uint32_t addr) {
    asm volatile("ldmatrix.sync.aligned.m8n8.x4.trans.shared.b16 {%0,%1,%2,%3}, [%4];"
                 : "=r"(r[0]), "=r"(r[1]), "=r"(r[2]), "=r"(r[3]) : "r"(addr));
}
__device__ __forceinline__ void mma_f16(float (&d)[4],
    const uint32_t (&a)[4], uint32_t b0, uint32_t b1)
{
    asm volatile(
        "mma.sync.aligned.m16n8k16.row.col.f32.f16.f16.f32 "
        "{%0,%1,%2,%3}, {%4,%5,%6,%7}, {%8,%9}, {%0,%1,%2,%3};"
        : "+f"(d[0]), "+f"(d[1]), "+f"(d[2]), "+f"(d[3])
        : "r"(a[0]), "r"(a[1]), "r"(a[2]), "r"(a[3]), "r"(b0), "r"(b1));
}
__device__ __forceinline__ void cpa16(uint32_t sd, const void* gs) {
    asm volatile("cp.async.cg.shared.global [%0], [%1], 16;" :: "r"(sd), "l"(gs));
}
__device__ __forceinline__ uint32_t pack2h(float f0, float f1) {
    __half h0 = __float2half(f0), h1 = __float2half(f1);
    return (uint32_t)*(uint16_t*)&h0 | ((uint32_t)*(uint16_t*)&h1 << 16);
}

// ---------------- mask compaction: per-batch prefix scan ----------------
__global__ __launch_bounds__(256) void compact_mask_kernel(
    const int* __restrict__ mask, int* __restrict__ gidx, int* __restrict__ cnt)
{
    __shared__ int wsum[8];
    const int b = blockIdx.x;
    const int tid = threadIdx.x, lane = tid & 31, wid = tid >> 5;
    int keep[8], local = 0;
#pragma unroll
    for (int i = 0; i < 8; i++) {
        keep[i] = (mask[b * S + tid * 8 + i] == 0);
        local += keep[i];
    }
    int v = local;
#pragma unroll
    for (int off = 1; off < 32; off <<= 1) {
        int n = __shfl_up_sync(0xffffffffu, v, off);
        if (lane >= off) v += n;
    }
    int excl = v - local;
    if (lane == 31) wsum[wid] = v;
    __syncthreads();
    if (wid == 0 && lane < 8) {
        int w = wsum[lane];
        int wv = w;
#pragma unroll
        for (int off = 1; off < 8; off <<= 1) {
            int n = __shfl_up_sync(0xffu, wv, off);
            if (lane >= off) wv += n;
        }
        wsum[lane] = wv - w;
        if (lane == 7) cnt[b] = wv;
    }
    __syncthreads();
    int base = wsum[wid] + excl;
#pragma unroll
    for (int i = 0; i < 8; i++)
        if (keep[i]) gidx[b * S + base++] = tid * 8 + i;
}

// ---------------- unified glue: converts + gather in ONE launch ----------
// grid (2048, 6):
//   z=0: q input convert (blocks 0..1023, 4 float4/thread)
//   z=1..4: weight converts (blocks 0..255)
//   z=5: K+V gather+convert (blocks 0..2047, 2 rows/block)
__global__ __launch_bounds__(256) void convert_all_kernel(
    FPtr5 X, const float* __restrict__ keyIn, const float* __restrict__ valIn,
    const int* __restrict__ gidx, const int* __restrict__ cnt,
    __half* __restrict__ ah, __half* __restrict__ wh,
    __half* __restrict__ Kh, __half* __restrict__ Vh)
{
    const int z = blockIdx.y;
    const int tid = threadIdx.x;
    if (z < 5) {
        const float* src = X.p[z];
        __half* dst = (z == 0) ? ah : wh + (size_t)(z - 1) * D * D;
        const int n4 = (z == 0) ? SZA / 4 : D * D / 4;
        int i = blockIdx.x * 1024 + tid;
        if (blockIdx.x * 1024 >= n4) return;
#pragma unroll
        for (int t = 0; t < 4; t++, i += 256) {
            if (i < n4) {
                float4 v = ((const float4*)src)[i];
                *(uint32_t*)&dst[i * 4 + 0] = pack2h(v.x, v.y);
                *(uint32_t*)&dst[i * 4 + 2] = pack2h(v.z, v.w);
            }
        }
    } else {
        // gather: 2 rows per block; 128 threads per row, 8 elems each
        const int g = blockIdx.x * 2 + (tid >> 7);   // global row 0..4095
        const int lt = tid & 127;
        const int b = g / S, pos = g % S;
        const int c = cnt[b];
        const int cpad = (c + 63) & ~63;
        if (pos >= cpad) return;
        const size_t dst = (size_t)(b * S + pos) * D + lt * 8;
        if (pos < c) {
            const size_t src = (size_t)(b * S + gidx[b * S + pos]) * D + lt * 8;
            float4 k0 = *(const float4*)&keyIn[src];
            float4 k1 = *(const float4*)&keyIn[src + 4];
            float4 v0 = *(const float4*)&valIn[src];
            float4 v1 = *(const float4*)&valIn[src + 4];
            *(uint4*)&Kh[dst] = make_uint4(pack2h(k0.x, k0.y), pack2h(k0.z, k0.w),
                                           pack2h(k1.x, k1.y), pack2h(k1.z, k1.w));
            *(uint4*)&Vh[dst] = make_uint4(pack2h(v0.x, v0.y), pack2h(v0.z, v0.w),
                                           pack2h(v1.x, v1.y), pack2h(v1.z, v1.w));
        } else {
            uint4 zz = make_uint4(0, 0, 0, 0);
            *(uint4*)&Kh[dst] = zz;
            *(uint4*)&Vh[dst] = zz;
        }
    }
}

// ---------------- fp16 single-pass GEMM: 128x128 tile, BK=64, 3 stages ----
#define BK 64
#define NCH (GK / BK)            // 16
#define ASTRIDE 144
#define BSTRIDE 272
#define OFF_B  (128 * ASTRIDE)   // 18432
#define STAGE_SB (OFF_B + 64 * BSTRIDE)  // 35840
#define GEMM_SMEM (3 * STAGE_SB)         // 107520

__device__ __forceinline__ void gemm_body(
    const __half* __restrict__ Ah,
    const __half* __restrict__ W,
    const float* __restrict__ bias, float* __restrict__ C,
    __half* __restrict__ Ch,
    char* smem)
{
    const uint32_t sbase = smem_u32(smem);
    const int tid = threadIdx.x;
    const int lane = tid & 31;
    const int wid = tid >> 5;
    const int warp_m = wid & 3;
    const int warp_n = wid >> 2;
    const int m0 = blockIdx.y * 128;
    const int n0 = blockIdx.x * 128;

    const __half* gAh = Ah + (size_t)m0 * GK;

    auto load_stage = [&](int stg, int k0) {
        uint32_t sb = sbase + stg * STAGE_SB;
#pragma unroll
        for (int j = 0; j < 4; j++) {
            int idx = tid + j * 256;
            int row = idx >> 3, ch = idx & 7;
            cpa16(sb + row * ASTRIDE + ch * 16,
                  gAh + (size_t)row * GK + k0 + ch * 8);
        }
#pragma unroll
        for (int j = 0; j < 4; j++) {
            int idx = tid + j * 256;
            int row = idx >> 4, ch = idx & 15;
            cpa16(sb + OFF_B + row * BSTRIDE + ch * 16,
                  W + (size_t)(k0 + row) * GN + n0 + ch * 8);
        }
        asm volatile("cp.async.commit_group;");
    };

    float acc[2][8][4];
#pragma unroll
    for (int i = 0; i < 2; i++)
#pragma unroll
        for (int j = 0; j < 8; j++)
#pragma unroll
            for (int v = 0; v < 4; v++) acc[i][j][v] = 0.f;

    load_stage(0, 0);
    load_stage(1, BK);

    const int a_row = lane & 15;
    const int a_kc  = lane >> 4;
    const int tr    = lane & 15;
    const int tc    = lane >> 4;

    int stg = 0;
    for (int ch = 0; ch < NCH; ch++) {
        if (ch < NCH - 1) asm volatile("cp.async.wait_group 1;");
        else              asm volatile("cp.async.wait_group 0;");
        __syncthreads();
        if (ch + 2 < NCH) {
            int ns = stg + 2; if (ns >= 3) ns -= 3;
            load_stage(ns, (ch + 2) * BK);
        }
        const uint32_t st = sbase + stg * STAGE_SB;
#pragma unroll
        for (int kc = 0; kc < 4; kc++) {
            uint32_t a_h[2][4], b_t[4][4];
#pragma unroll
            for (int mt = 0; mt < 2; mt++) {
                uint32_t ro = (warp_m * 32 + mt * 16 + a_row) * ASTRIDE
                            + (kc * 2 + a_kc) * 16;
                ldsm_x4(a_h[mt], st + ro);
            }
#pragma unroll
            for (int ng = 0; ng < 4; ng++) {
                uint32_t ro = (kc * 16 + tr) * BSTRIDE
                            + warp_n * 128 + ng * 32 + tc * 16;
                ldsm_x4_t(b_t[ng], st + OFF_B + ro);
            }
#pragma unroll
            for (int mt = 0; mt < 2; mt++)
#pragma unroll
                for (int ng = 0; ng < 4; ng++) {
                    mma_f16(acc[mt][ng * 2 + 0], a_h[mt], b_t[ng][0], b_t[ng][1]);
                    mma_f16(acc[mt][ng * 2 + 1], a_h[mt], b_t[ng][2], b_t[ng][3]);
                }
        }
        if (++stg == 3) stg = 0;
    }

    const int grp = lane >> 2, tg = lane & 3;
#pragma unroll
    for (int mt = 0; mt < 2; mt++) {
        int r0 = m0 + warp_m * 32 + mt * 16 + grp;
#pragma unroll
        for (int nt = 0; nt < 8; nt++) {
            int c = n0 + warp_n * 64 + nt * 8 + tg * 2;
            float2 b2 = *(const float2*)&bias[c];
            float o00 = acc[mt][nt][0] + b2.x;
            float o01 = acc[mt][nt][1] + b2.y;
            float o10 = acc[mt][nt][2] + b2.x;
            float o11 = acc[mt][nt][3] + b2.y;
            if (C) {
                *(float2*)&C[(size_t)r0 * GN + c] = make_float2(o00, o01);
                *(float2*)&C[(size_t)(r0 + 8) * GN + c] = make_float2(o10, o11);
            } else {
                *(uint32_t*)&Ch[(size_t)r0 * GN + c] = pack2h(o00, o01);
                *(uint32_t*)&Ch[(size_t)(r0 + 8) * GN + c] = pack2h(o10, o11);
            }
        }
    }
}

struct QKVBias { const float* p[3]; };

__global__ __launch_bounds__(256, 2) void qkv_gemm_kernel(
    const __half* __restrict__ AhB, const __half* __restrict__ WhB,
    QKVBias bias, const int* __restrict__ cnt,
    __half* __restrict__ ChB)
{
    extern __shared__ char smem[];
    const int z = blockIdx.z;
    if (z > 0) {
        const int m0 = blockIdx.y * 128;
        const int b = m0 / S;
        const int cpad = (cnt[b] + 63) & ~63;
        if ((m0 % S) >= cpad) return;
    }
    gemm_body(AhB + (size_t)z * SZA, WhB + (size_t)z * D * D,
              bias.p[z], nullptr, ChB + (size_t)z * SZA, smem);
}

__global__ __launch_bounds__(256, 2) void oproj_gemm_kernel(
    const __half* __restrict__ Ah, const __half* __restrict__ Wh,
    const float* __restrict__ bias, float* __restrict__ C)
{
    extern __shared__ char smem[];
    gemm_body(Ah, Wh, bias, C, nullptr, smem);
}

// ---------------- Attention: fp16, 4-stage, distance-3 prefetch ----------
#define ASTG 18432
#define AT_VH 9216
#define ATTN_SMEM (4 * ASTG)   // 73728

__global__ __launch_bounds__(256, 2) void attn_mma_kernel(
    const __half* __restrict__ Qh,
    const __half* __restrict__ Kh, const __half* __restrict__ Vh,
    const int* __restrict__ cnt,
    __half* __restrict__ Ch)
{
    extern __shared__ char smem[];
    const uint32_t sb = smem_u32(smem);
    const int tid = threadIdx.x, lane = tid & 31, wid = tid >> 5;
    const int b = blockIdx.z, h = blockIdx.y, q0 = blockIdx.x * 128;
    const int cn = cnt[b];
    const int nch = (cn + 63) >> 6;

    // ---- stage Q tile into smem once, ldsm to fragments ----
#pragma unroll
    for (int t = 0; t < 4; t++) {
        int idx = tid + t * 256;
        int row = idx >> 3, ch = idx & 7;
        const __half* src = Qh + (size_t)(b * S + q0 + row) * D + h * DK + ch * 8;
        *(uint4*)(smem + row * 144 + ch * 16) = *(const uint4*)src;
    }
    __syncthreads();
    uint32_t qfh[4][4];
    {
        int r = wid * 16 + (lane & 15);
        int hc = lane >> 4;
#pragma unroll
        for (int c = 0; c < 4; c++)
            ldsm_x4(qfh[c], sb + r * 144 + (c * 2 + hc) * 16);
    }
    __syncthreads();

    auto load_stage = [&](int stg, int kk) {
        uint32_t base = sb + stg * ASTG;
#pragma unroll
        for (int t = 0; t < 4; t++) {
            int idx = tid + t * 256;
            int tile = idx >> 9;
            int c = idx & 511;
            int row = c >> 3, ch = c & 7;
            const __half* g = (tile == 0 ? Kh : Vh)
                + (size_t)(b * S + kk + row) * D + h * DK + ch * 8;
            cpa16(base + tile * 9216 + row * 144 + ch * 16, g);
        }
        asm volatile("cp.async.commit_group;");
    };

    float acc[8][4];
#pragma unroll
    for (int j = 0; j < 8; j++)
#pragma unroll
        for (int v = 0; v < 4; v++) acc[j][v] = 0.f;
    float m0r = -1e30f, m1r = -1e30f, l0r = 0.f, l1r = 0.f;
    const float scale = 0.125f;

    if (nch >= 1) load_stage(0, 0);
    if (nch >= 2) load_stage(1, 64);
    if (nch >= 3) load_stage(2, 128);

    const int bg    = lane >> 3;
    const int b_row = ((bg >> 1) * 8) + (lane & 7);
    const int b_kc  = bg & 1;
    const int tr    = lane & 15;
    const int tc    = lane >> 4;
    const int jlane = (lane & 3) * 2;

    for (int it = 0; it < nch; it++) {
        const int stg = it & 3;
        // wait until chunk it's loads are complete (outstanding beyond it:
        // up to 2 younger chunks when mid-stream)
        int rem = nch - 1 - it;
        if (rem >= 2)      asm volatile("cp.async.wait_group 2;");
        else if (rem == 1) asm volatile("cp.async.wait_group 1;");
        else               asm volatile("cp.async.wait_group 0;");
        __syncthreads();
        // distance-3 prefetch into stage (it+3)&3 = stage used at it-1
        if (it + 3 < nch) load_stage((it + 3) & 3, (it + 3) * 64);

        const uint32_t st = sb + stg * ASTG;

        float s[8][4];
#pragma unroll
        for (int j = 0; j < 8; j++)
#pragma unroll
            for (int v = 0; v < 4; v++) s[j][v] = 0.f;
#pragma unroll
        for (int c = 0; c < 4; c++) {
#pragma unroll
            for (int np = 0; np < 4; np++) {
                uint32_t kbh[4];
                uint32_t ro = (np * 16 + b_row) * 144 + (c * 2 + b_kc) * 16;
                ldsm_x4(kbh, st + ro);
                mma_f16(s[np * 2 + 0], qfh[c], kbh[0], kbh[1]);
                mma_f16(s[np * 2 + 1], qfh[c], kbh[2], kbh[3]);
            }
        }

        // ---- online softmax; masking only on the final (tail) chunk ----
        float mx0 = -1e30f, mx1 = -1e30f;
        if (it == nch - 1) {
            const int jbase = it * 64 + jlane;
#pragma unroll
            for (int nt = 0; nt < 8; nt++) {
                int j0 = jbase + nt * 8;
                bool k0m = (j0 >= cn), k1m = (j0 + 1 >= cn);
                s[nt][0] = k0m ? -1e30f : s[nt][0] * scale;
                s[nt][1] = k1m ? -1e30f : s[nt][1] * scale;
                s[nt][2] = k0m ? -1e30f : s[nt][2] * scale;
                s[nt][3] = k1m ? -1e30f : s[nt][3] * scale;
                mx0 = fmaxf(mx0, fmaxf(s[nt][0], s[nt][1]));
                mx1 = fmaxf(mx1, fmaxf(s[nt][2], s[nt][3]));
            }
        } else {
#pragma unroll
            for (int nt = 0; nt < 8; nt++) {
                s[nt][0] *= scale; s[nt][1] *= scale;
                s[nt][2] *= scale; s[nt][3] *= scale;
                mx0 = fmaxf(mx0, fmaxf(s[nt][0], s[nt][1]));
                mx1 = fmaxf(mx1, fmaxf(s[nt][2], s[nt][3]));
            }
        }
#pragma unroll
        for (int off = 1; off < 4; off <<= 1) {
            mx0 = fmaxf(mx0, __shfl_xor_sync(0xffffffffu, mx0, off));
            mx1 = fmaxf(mx1, __shfl_xor_sync(0xffffffffu, mx1, off));
        }
        float mn0 = fmaxf(m0r, mx0), mn1 = fmaxf(m1r, mx1);
        float cr0 = __expf(m0r - mn0), cr1 = __expf(m1r - mn1);
        float sum0 = 0.f, sum1 = 0.f;
        if (it == nch - 1) {
#pragma unroll
            for (int nt = 0; nt < 8; nt++) {
                float p0 = (s[nt][0] > -5e29f) ? __expf(s[nt][0] - mn0) : 0.f;
                float p1 = (s[nt][1] > -5e29f) ? __expf(s[nt][1] - mn0) : 0.f;
                float p2 = (s[nt][2] > -5e29f) ? __expf(s[nt][2] - mn1) : 0.f;
                float p3 = (s[nt][3] > -5e29f) ? __expf(s[nt][3] - mn1) : 0.f;
                s[nt][0] = p0; s[nt][1] = p1; s[nt][2] = p2; s[nt][3] = p3;
                sum0 += p0 + p1;
                sum1 += p2 + p3;
            }
        } else {
#pragma unroll
            for (int nt = 0; nt < 8; nt++) {
                float p0 = __expf(s[nt][0] - mn0);
                float p1 = __expf(s[nt][1] - mn0);
                float p2 = __expf(s[nt][2] - mn1);
                float p3 = __expf(s[nt][3] - mn1);
                s[nt][0] = p0; s[nt][1] = p1; s[nt][2] = p2; s[nt][3] = p3;
                sum0 += p0 + p1;
                sum1 += p2 + p3;
            }
        }
#pragma unroll
        for (int off = 1; off < 4; off <<= 1) {
            sum0 += __shfl_xor_sync(0xffffffffu, sum0, off);
            sum1 += __shfl_xor_sync(0xffffffffu, sum1, off);
        }
        l0r = l0r * cr0 + sum0;
        l1r = l1r * cr1 + sum1;
        m0r = mn0; m1r = mn1;
#pragma unroll
        for (int nt = 0; nt < 8; nt++) {
            acc[nt][0] *= cr0; acc[nt][1] *= cr0;
            acc[nt][2] *= cr1; acc[nt][3] *= cr1;
        }

        uint32_t pah[4][4];
#pragma unroll
        for (int c = 0; c < 4; c++) {
            pah[c][0] = pack2h(s[2 * c][0],     s[2 * c][1]);
            pah[c][1] = pack2h(s[2 * c][2],     s[2 * c][3]);
            pah[c][2] = pack2h(s[2 * c + 1][0], s[2 * c + 1][1]);
            pah[c][3] = pack2h(s[2 * c + 1][2], s[2 * c + 1][3]);
        }

#pragma unroll
        for (int c = 0; c < 4; c++) {
#pragma unroll
            for (int np = 0; np < 4; np++) {
                uint32_t vbh[4];
                uint32_t ro = (c * 16 + tr) * 144 + np * 32 + tc * 16;
                ldsm_x4_t(vbh, st + AT_VH + ro);
                mma_f16(acc[np * 2 + 0], pah[c], vbh[0], vbh[1]);
                mma_f16(acc[np * 2 + 1], pah[c], vbh[2], vbh[3]);
            }
        }
    }

    // ---- epilogue: ctx as fp16 ----
    float inv0 = (l0r > 0.f) ? (1.f / l0r) : 0.f;
    float inv1 = (l1r > 0.f) ? (1.f / l1r) : 0.f;
    int r0 = q0 + wid * 16 + (lane >> 2);
#pragma unroll
    for (int nt = 0; nt < 8; nt++) {
        int c = h * DK + nt * 8 + (lane & 3) * 2;
        size_t o0 = (size_t)(b * S + r0) * D + c;
        size_t o1 = (size_t)(b * S + r0 + 8) * D + c;
        *(uint32_t*)&Ch[o0] = pack2h(acc[nt][0] * inv0, acc[nt][1] * inv0);
        *(uint32_t*)&Ch[o1] = pack2h(acc[nt][2] * inv1, acc[nt][3] * inv1);
    }
}

// ---------------- launch ----------------
extern "C" void kernel_launch(void* const* d_in, const int* in_sizes, int n_in,
                              void* d_out, int out_size)
{
    const float* query = (const float*)d_in[0];
    const float* key   = (const float*)d_in[1];
    const float* value = (const float*)d_in[2];
    const int*   mask  = (const int*)d_in[3];
    const float* Wq = (const float*)d_in[4];
    const float* bq = (const float*)d_in[5];
    const float* Wk = (const float*)d_in[6];
    const float* bk = (const float*)d_in[7];
    const float* Wv = (const float*)d_in[8];
    const float* bv = (const float*)d_in[9];
    const float* Wo = (const float*)d_in[10];
    const float* bo = (const float*)d_in[11];
    float* out = (float*)d_out;

    __half *ah, *wh;
    int *gidx, *cnt;
    cudaGetSymbolAddress((void**)&ah, g_Ah);
    cudaGetSymbolAddress((void**)&wh, g_Wh);
    cudaGetSymbolAddress((void**)&gidx, g_gidx);
    cudaGetSymbolAddress((void**)&cnt, g_cnt);

    static int attr_set = 0;
    if (!attr_set) {
        cudaFuncSetAttribute(qkv_gemm_kernel,
                             cudaFuncAttributeMaxDynamicSharedMemorySize, GEMM_SMEM);
        cudaFuncSetAttribute(oproj_gemm_kernel,
                             cudaFuncAttributeMaxDynamicSharedMemorySize, GEMM_SMEM);
        cudaFuncSetAttribute(attn_mma_kernel,
                             cudaFuncAttributeMaxDynamicSharedMemorySize, ATTN_SMEM);
        attr_set = 1;
    }

    // 0: mask compaction
    compact_mask_kernel<<<B, 256>>>(mask, gidx, cnt);

    // 1: all converts + K/V gather in one launch
    FPtr5 cin;
    cin.p[0] = query; cin.p[1] = Wq; cin.p[2] = Wk; cin.p[3] = Wv; cin.p[4] = Wo;
    dim3 ca_grid(M_ROWS / 2, 6);   // (2048, 6)
    convert_all_kernel<<<ca_grid, 256>>>(
        cin, key, value, gidx, cnt,
        ah, wh, ah + (size_t)1 * SZA, ah + (size_t)2 * SZA);

    // 2: batched projections (single-pass; K/V early-exit past compact rows)
    QKVBias qb; qb.p[0] = bq; qb.p[1] = bk; qb.p[2] = bv;
    dim3 qkv_grid(GN / 128, M_ROWS / 128, 3);
    qkv_gemm_kernel<<<qkv_grid, 256, GEMM_SMEM>>>(
        ah, wh, qb, cnt, ah + (size_t)3 * SZA);

    // 3: attention -> ctx slot 6
    dim3 attn_grid(S / 128, H, B);
    attn_mma_kernel<<<attn_grid, 256, ATTN_SMEM>>>(
        ah + (size_t)3 * SZA,
        ah + (size_t)4 * SZA,
        ah + (size_t)5 * SZA,
        cnt,
        ah + (size_t)6 * SZA);

    // 4: output projection (fp32 out, single wave)
    dim3 gemm_grid(GN / 128, M_ROWS / 128);
    oproj_gemm_kernel<<<gemm_grid, 256, GEMM_SMEM>>>(
        ah + (size_t)6 * SZA, wh + (size_t)3 * D * D, bo, out);
}